// round 12
// baseline (speedup 1.0000x reference)
#include <cuda_runtime.h>
#include <cstdint>
#include <math.h>

#define LC   2048
#define CINV 0.35355339059327373f   // 1/(2*sqrt(2))

// Transposed wavelet weights, f32: [which][k][i*64+o]
__device__ float g_wt[2][(size_t)LC * 4096];

__device__ __forceinline__ float gelu_tanh(float v) {
    float z = 0.7978845608028654f * (v + 0.044715f * v * v * v);
    float t;
    asm("tanh.approx.f32 %0, %1;" : "=f"(t) : "f"(z));
    return 0.5f * v * (1.0f + t);
}

// ---------------------------------------------------------------------------
// Kernel 1: transpose w_approx / w_detail (i,o,l) -> (l, i*64+o), f32
// ---------------------------------------------------------------------------
__global__ void transpose_w_kernel(const float* __restrict__ wA,
                                   const float* __restrict__ wD) {
    __shared__ float tile[32][33];
    const float* src = (blockIdx.z == 0) ? wA : wD;
    float* dst = g_wt[blockIdx.z];
    int lbase  = blockIdx.x * 32;
    int iobase = blockIdx.y * 32;
    int tx = threadIdx.x, ty = threadIdx.y;   // block (32, 8)
#pragma unroll
    for (int r = 0; r < 32; r += 8)
        tile[ty + r][tx] = src[(size_t)(iobase + ty + r) * LC + (lbase + tx)];
    __syncthreads();
#pragma unroll
    for (int r = 0; r < 32; r += 8)
        dst[(size_t)(lbase + ty + r) * 4096 + (iobase + tx)] = tile[tx][ty + r];
}

// ---------------------------------------------------------------------------
// Kernel 2: fully fused, 57344 B smem -> 4 CTAs/SM, W_t streamed from gmem.
// Grid 4096 = (k, half). 256 threads, 16 batches x 8 rows x 64 ch.
// smem: [0,8192)     xs  [16 b][512]  (f32, unpadded; all hot reads are
//                                      broadcast or unit-stride)
//       [8192,12288) shrW: phase1-2 uv [2][64 i][21] (2688 fl);
//                    phase3+  wsk f32 (W_skip + I) (4096 fl)
//       [12288,14336) corr [2][16 b][64 o]
// ---------------------------------------------------------------------------
__global__ __launch_bounds__(256, 4) void fused_kernel(
    const float* __restrict__ x, const float* __restrict__ Ws,
    const float* __restrict__ bsk, float* __restrict__ out)
{
    extern __shared__ float sm[];
    float* xs   = sm;            // 8192 fl
    float* shrW = sm + 8192;     // 4096 fl (uv overlay, then wsk)
    float* corr = sm + 12288;    // 2048 fl

    const int k    = blockIdx.x >> 1;
    const int half = blockIdx.x & 1;
    const int tid  = threadIdx.x;
    const int cg   = (tid & 15) << 2;

    // bias in registers (256 B table, L1-resident)
    const float4 Bb = __ldg((const float4*)bsk + (tid & 15));

    // ---- Phase 0: load xs ----
    {
        const float4* x4  = (const float4*)x;
        float4*       xs4 = (float4*)xs;
#pragma unroll
        for (int it = 0; it < 8; it++) {
            int idx = tid + it * 256;           // 0..2047 float4s
            int bl = idx >> 7, r = idx & 127;
            int b  = half * 16 + bl;
            xs4[bl * 128 + r] = x4[(size_t)b * 262144 + (size_t)k * 128 + r];
        }
    }
    __syncthreads();

    // ---- Phase 1: u/v from xs into shrW-overlay uv[which][i][21] ----
    {
        float* uv = shrW;
#pragma unroll
        for (int it = 0; it < 4; it++) {
            int p  = tid + it * 256;            // 0..1023  (bl, i)
            int i  = p & 63, bl = p >> 6;
            const float* xb = xs + bl * 512 + i;
            float e = 0.f, d = 0.f;
#pragma unroll
            for (int j = 0; j < 4; j++) { e += xb[j * 64]; d += xb[(j + 4) * 64]; }
            uv[i * 21 + bl]        = CINV * (e + d);
            uv[1344 + i * 21 + bl] = CINV * (e - d);
        }
    }
    __syncthreads();

    // ---- Phase 2: corrections; W_t f32 streamed from gmem (coalesced, L1/L2 hit)
    {
        const int which = tid >> 7;
        const int r  = tid & 127;
        const int bl = r >> 3;
        const int og = (r & 7) * 8;
        const float4* Wg = (const float4*)(g_wt[which] + (size_t)k * 4096) + (og >> 2);
        const float*  U  = shrW + which * 1344;

        float acc[8] = {};
#pragma unroll 8
        for (int i = 0; i < 64; i++) {
            float u = U[i * 21 + bl];
            float4 w0 = __ldg(Wg + i * 16);
            float4 w1 = __ldg(Wg + i * 16 + 1);
            acc[0] = fmaf(u, w0.x, acc[0]);
            acc[1] = fmaf(u, w0.y, acc[1]);
            acc[2] = fmaf(u, w0.z, acc[2]);
            acc[3] = fmaf(u, w0.w, acc[3]);
            acc[4] = fmaf(u, w1.x, acc[4]);
            acc[5] = fmaf(u, w1.y, acc[5]);
            acc[6] = fmaf(u, w1.z, acc[6]);
            acc[7] = fmaf(u, w1.w, acc[7]);
        }
        float* cp = corr + which * 1024 + bl * 64 + og;
#pragma unroll
        for (int e = 0; e < 8; e++)
            cp[e] = CINV * (acc[e] - U[(og + e) * 21 + bl]);
    }
    __syncthreads();    // uv dead

    // ---- Phase 3: wsk = (W_skip + I) into shrW ----
#pragma unroll
    for (int it = 0; it < 16; it++) {
        int i = tid + it * 256;             // 0..4095
        float v = Ws[i];
        if ((i >> 6) == (i & 63)) v += 1.0f;
        shrW[i] = v;
    }
    __syncthreads();

    // ---- Phase 4: GEMM + epilogue (proven R8 8x4 / 2-kk inner loop) ----
    const int bl = tid >> 4;
    const float* xb = xs + bl * 512;

    float acc[8][4] = {};
#pragma unroll 8
    for (int kk = 0; kk < 64; kk += 2) {
        float4 w0 = *(const float4*)(shrW + kk * 64 + cg);
        float4 w1 = *(const float4*)(shrW + (kk + 1) * 64 + cg);
        float2 xv[8];
#pragma unroll
        for (int j = 0; j < 8; j++)
            xv[j] = *(const float2*)(xb + j * 64 + kk);
#pragma unroll
        for (int j = 0; j < 8; j++) {
            acc[j][0] = fmaf(xv[j].x, w0.x, acc[j][0]);
            acc[j][0] = fmaf(xv[j].y, w1.x, acc[j][0]);
            acc[j][1] = fmaf(xv[j].x, w0.y, acc[j][1]);
            acc[j][1] = fmaf(xv[j].y, w1.y, acc[j][1]);
            acc[j][2] = fmaf(xv[j].x, w0.z, acc[j][2]);
            acc[j][2] = fmaf(xv[j].y, w1.z, acc[j][2]);
            acc[j][3] = fmaf(xv[j].x, w0.w, acc[j][3]);
            acc[j][3] = fmaf(xv[j].y, w1.w, acc[j][3]);
        }
    }

    float4 A  = *(const float4*)(corr + bl * 64 + cg);
    float4 Dv = *(const float4*)(corr + 1024 + bl * 64 + cg);
    const int b = half * 16 + bl;
    float* op = out + ((size_t)b * 16384 + (size_t)k * 8) * 64 + cg;
#pragma unroll
    for (int j = 0; j < 8; j++) {
        float sgn = (j < 4) ? 1.f : -1.f;
        float4 rv;
        rv.x = gelu_tanh(acc[j][0] + A.x + sgn * Dv.x + Bb.x);
        rv.y = gelu_tanh(acc[j][1] + A.y + sgn * Dv.y + Bb.y);
        rv.z = gelu_tanh(acc[j][2] + A.z + sgn * Dv.z + Bb.z);
        rv.w = gelu_tanh(acc[j][3] + A.w + sgn * Dv.w + Bb.w);
        *(float4*)(op + j * 64) = rv;
    }
}

extern "C" void kernel_launch(void* const* d_in, const int* in_sizes, int n_in,
                              void* d_out, int out_size) {
    const float* x  = (const float*)d_in[0];   // (32, 16384, 64)
    const float* wA = (const float*)d_in[1];   // (64, 64, 2048)
    const float* wD = (const float*)d_in[2];   // (64, 64, 2048)
    const float* Ws = (const float*)d_in[3];   // (64, 64)
    const float* bs = (const float*)d_in[4];   // (64,)
    float* out = (float*)d_out;

    cudaFuncSetAttribute(fused_kernel,
        cudaFuncAttributeMaxDynamicSharedMemorySize, 57344);

    dim3 tb(32, 8), tg(LC / 32, 4096 / 32, 2);
    transpose_w_kernel<<<tg, tb>>>(wA, wD);

    fused_kernel<<<2 * LC, 256, 57344>>>(x, Ws, bs, out);
}

// round 13
// speedup vs baseline: 1.4624x; 1.4624x over previous
#include <cuda_runtime.h>
#include <cuda_bf16.h>
#include <cstdint>
#include <math.h>

#define LC   2048
#define CINV 0.35355339059327373f   // 1/(2*sqrt(2))

// Transposed wavelet weights, bf16: [which][k][i*64+o]
__device__ __nv_bfloat16 g_wt[2][(size_t)LC * 4096];

__device__ __forceinline__ float gelu_tanh(float v) {
    float z = 0.7978845608028654f * (v + 0.044715f * v * v * v);
    float t;
    asm("tanh.approx.f32 %0, %1;" : "=f"(t) : "f"(z));
    return 0.5f * v * (1.0f + t);
}

// ---------------------------------------------------------------------------
// Kernel 1: transpose w_approx / w_detail (i,o,l) -> (l, i*64+o), f32 -> bf16
// ---------------------------------------------------------------------------
__global__ void transpose_w_kernel(const float* __restrict__ wA,
                                   const float* __restrict__ wD) {
    __shared__ float tile[32][33];
    const float* src = (blockIdx.z == 0) ? wA : wD;
    __nv_bfloat16* dst = g_wt[blockIdx.z];
    int lbase  = blockIdx.x * 32;
    int iobase = blockIdx.y * 32;
    int tx = threadIdx.x, ty = threadIdx.y;   // block (32, 8)
#pragma unroll
    for (int r = 0; r < 32; r += 8)
        tile[ty + r][tx] = src[(size_t)(iobase + ty + r) * LC + (lbase + tx)];
    __syncthreads();
#pragma unroll
    for (int r = 0; r < 32; r += 8)
        dst[(size_t)(lbase + ty + r) * 4096 + (iobase + tx)] =
            __float2bfloat16(tile[tx][ty + r]);
}

// ---------------------------------------------------------------------------
// Kernel 2: fully fused (R8 layout; u/v fused into x-load; phase-2 unpack
// amortized over 2 batches). Grid 4096 = (k, half). 256 threads,
// 16 batches x 8 rows x 64 ch. 3 CTAs/SM, 68608 B smem.
// ---------------------------------------------------------------------------
__global__ __launch_bounds__(256, 3) void fused_kernel(
    const float* __restrict__ x, const float* __restrict__ Ws,
    const float* __restrict__ bsk, float* __restrict__ out)
{
    extern __shared__ float sm[];
    float* xs   = sm;            // 16 b * 520 (8x64 + pad 8)   = 8320 fl
    float* shrW = sm + 8320;     // 4096 fl: bf16 W_t [2][4096] then f32 wsk
    float* uv   = sm + 12416;    // [2][64 i][21]               = 2688 fl
    float* corr = sm + 15104;    // [2][16 b][64 o]             = 2048 fl

    const int k    = blockIdx.x >> 1;
    const int half = blockIdx.x & 1;
    const int tid  = threadIdx.x;
    const int bl   = tid >> 4;          // 0..15 (batch within block)
    const int c4   = tid & 15;          // float4 channel group
    const int cg   = c4 << 2;

    // bias in registers
    const float4 Bb = __ldg((const float4*)bsk + c4);

    // ---- Phase 0a: W_t bf16 -> shrW ----
    {
        uint4* dstw = (uint4*)shrW;
#pragma unroll
        for (int it = 0; it < 2; it++) {
            int i = tid + it * 256;         // 0..511 uint4 per which
            dstw[i]       = ((const uint4*)(g_wt[0] + (size_t)k * 4096))[i];
            dstw[512 + i] = ((const uint4*)(g_wt[1] + (size_t)k * 4096))[i];
        }
    }

    // ---- Phase 0b: x load + u/v accumulation in registers ----
    {
        const int b = half * 16 + bl;
        const float4* xg = (const float4*)(x + ((size_t)b * 16384
                                                + (size_t)k * 8) * 64) + c4;
        float4* xs4 = (float4*)xs + bl * 130 + c4;
        float4 e = make_float4(0.f, 0.f, 0.f, 0.f);
        float4 d = make_float4(0.f, 0.f, 0.f, 0.f);
#pragma unroll
        for (int j = 0; j < 8; j++) {
            float4 v = __ldg(xg + j * 16);
            xs4[j * 16] = v;
            if (j < 4) { e.x += v.x; e.y += v.y; e.z += v.z; e.w += v.w; }
            else       { d.x += v.x; d.y += v.y; d.z += v.z; d.w += v.w; }
        }
        float* up = uv + cg * 21 + bl;
        up[0 * 21]          = CINV * (e.x + d.x);
        up[1 * 21]          = CINV * (e.y + d.y);
        up[2 * 21]          = CINV * (e.z + d.z);
        up[3 * 21]          = CINV * (e.w + d.w);
        up[1344 + 0 * 21]   = CINV * (e.x - d.x);
        up[1344 + 1 * 21]   = CINV * (e.y - d.y);
        up[1344 + 2 * 21]   = CINV * (e.z - d.z);
        up[1344 + 3 * 21]   = CINV * (e.w - d.w);
    }
    __syncthreads();

    // ---- Phase 2: corrections. thread -> (which, batch-pair, 4 outputs) ----
    {
        const int which = tid >> 7;
        const int r   = tid & 127;
        const int bp  = r >> 4;             // batch pair: b0=2bp, b1=2bp+1
        const int og  = (r & 15) * 4;
        const int b0  = 2 * bp, b1 = 2 * bp + 1;
        const __nv_bfloat16* W = (const __nv_bfloat16*)shrW + which * 4096;
        const float* U = uv + which * 1344;

        float a0[4] = {}, a1[4] = {};
#pragma unroll 8
        for (int i = 0; i < 64; i++) {
            uint2 wv = *(const uint2*)(W + i * 64 + og);   // 4 bf16
            float2 w01 = __bfloat1622float2(*(const __nv_bfloat162*)&wv.x);
            float2 w23 = __bfloat1622float2(*(const __nv_bfloat162*)&wv.y);
            float u0 = U[i * 21 + b0];
            float u1 = U[i * 21 + b1];
            a0[0] = fmaf(u0, w01.x, a0[0]);
            a0[1] = fmaf(u0, w01.y, a0[1]);
            a0[2] = fmaf(u0, w23.x, a0[2]);
            a0[3] = fmaf(u0, w23.y, a0[3]);
            a1[0] = fmaf(u1, w01.x, a1[0]);
            a1[1] = fmaf(u1, w01.y, a1[1]);
            a1[2] = fmaf(u1, w23.x, a1[2]);
            a1[3] = fmaf(u1, w23.y, a1[3]);
        }
        float* cp0 = corr + which * 1024 + b0 * 64 + og;
        float* cp1 = corr + which * 1024 + b1 * 64 + og;
#pragma unroll
        for (int e = 0; e < 4; e++) {
            cp0[e] = CINV * (a0[e] - U[(og + e) * 21 + b0]);
            cp1[e] = CINV * (a1[e] - U[(og + e) * 21 + b1]);
        }
    }
    __syncthreads();

    // ---- Phase 3: overwrite shrW with (W_skip + I) as f32 ----
#pragma unroll
    for (int it = 0; it < 16; it++) {
        int i = tid + it * 256;             // 0..4095
        float v = Ws[i];
        if ((i >> 6) == (i & 63)) v += 1.0f;
        shrW[i] = v;
    }
    __syncthreads();

    // ---- Phase 4: GEMM + epilogue (proven R8 8x4 / 2-kk inner loop) ----
    const float* xb = xs + bl * 520;

    float acc[8][4] = {};
#pragma unroll 8
    for (int kk = 0; kk < 64; kk += 2) {
        float4 w0 = *(const float4*)(shrW + kk * 64 + cg);
        float4 w1 = *(const float4*)(shrW + (kk + 1) * 64 + cg);
        float2 xv[8];
#pragma unroll
        for (int j = 0; j < 8; j++)
            xv[j] = *(const float2*)(xb + j * 64 + kk);
#pragma unroll
        for (int j = 0; j < 8; j++) {
            acc[j][0] = fmaf(xv[j].x, w0.x, acc[j][0]);
            acc[j][0] = fmaf(xv[j].y, w1.x, acc[j][0]);
            acc[j][1] = fmaf(xv[j].x, w0.y, acc[j][1]);
            acc[j][1] = fmaf(xv[j].y, w1.y, acc[j][1]);
            acc[j][2] = fmaf(xv[j].x, w0.z, acc[j][2]);
            acc[j][2] = fmaf(xv[j].y, w1.z, acc[j][2]);
            acc[j][3] = fmaf(xv[j].x, w0.w, acc[j][3]);
            acc[j][3] = fmaf(xv[j].y, w1.w, acc[j][3]);
        }
    }

    float4 A  = *(const float4*)(corr + bl * 64 + cg);
    float4 Dv = *(const float4*)(corr + 1024 + bl * 64 + cg);
    const int b = half * 16 + bl;
    float* op = out + ((size_t)b * 16384 + (size_t)k * 8) * 64 + cg;
#pragma unroll
    for (int j = 0; j < 8; j++) {
        float sgn = (j < 4) ? 1.f : -1.f;
        float4 rv;
        rv.x = gelu_tanh(acc[j][0] + A.x + sgn * Dv.x + Bb.x);
        rv.y = gelu_tanh(acc[j][1] + A.y + sgn * Dv.y + Bb.y);
        rv.z = gelu_tanh(acc[j][2] + A.z + sgn * Dv.z + Bb.z);
        rv.w = gelu_tanh(acc[j][3] + A.w + sgn * Dv.w + Bb.w);
        *(float4*)(op + j * 64) = rv;
    }
}

extern "C" void kernel_launch(void* const* d_in, const int* in_sizes, int n_in,
                              void* d_out, int out_size) {
    const float* x  = (const float*)d_in[0];   // (32, 16384, 64)
    const float* wA = (const float*)d_in[1];   // (64, 64, 2048)
    const float* wD = (const float*)d_in[2];   // (64, 64, 2048)
    const float* Ws = (const float*)d_in[3];   // (64, 64)
    const float* bs = (const float*)d_in[4];   // (64,)
    float* out = (float*)d_out;

    cudaFuncSetAttribute(fused_kernel,
        cudaFuncAttributeMaxDynamicSharedMemorySize, 68608);

    dim3 tb(32, 8), tg(LC / 32, 4096 / 32, 2);
    transpose_w_kernel<<<tg, tb>>>(wA, wD);

    fused_kernel<<<2 * LC, 256, 68608>>>(x, Ws, bs, out);
}

// round 14
// speedup vs baseline: 1.8078x; 1.2362x over previous
#include <cuda_runtime.h>
#include <cuda_bf16.h>
#include <cstdint>
#include <math.h>

#define LC   2048
#define CINV 0.35355339059327373f   // 1/(2*sqrt(2))

// Transposed wavelet weights, bf16: [which][k][i*64+o]
__device__ __nv_bfloat16 g_wt[2][(size_t)LC * 4096];

__device__ __forceinline__ float gelu_tanh(float v) {
    float z = 0.7978845608028654f * (v + 0.044715f * v * v * v);
    float t;
    asm("tanh.approx.f32 %0, %1;" : "=f"(t) : "f"(z));
    return 0.5f * v * (1.0f + t);
}

__device__ __forceinline__ unsigned pack_bf16(float a, float b) {
    __nv_bfloat162 h = __float22bfloat162_rn(make_float2(a, b));
    return *reinterpret_cast<unsigned*>(&h);
}
__device__ __forceinline__ float2 unpack_bf16(unsigned u) {
    return __bfloat1622float2(*reinterpret_cast<__nv_bfloat162*>(&u));
}

// warp mma: D(f32 m16n8) += A(bf16 m16k16, row) * B(bf16 k16n8, col)
__device__ __forceinline__ void mma_bf16(float* d, const unsigned* a, const unsigned* b) {
    asm("mma.sync.aligned.m16n8k16.row.col.f32.bf16.bf16.f32 "
        "{%0,%1,%2,%3}, {%4,%5,%6,%7}, {%8,%9}, {%0,%1,%2,%3};"
        : "+f"(d[0]), "+f"(d[1]), "+f"(d[2]), "+f"(d[3])
        : "r"(a[0]), "r"(a[1]), "r"(a[2]), "r"(a[3]), "r"(b[0]), "r"(b[1]));
}

// ---------------------------------------------------------------------------
// Kernel 1: transpose w_approx / w_detail (i,o,l) -> (l, i*64+o), f32 -> bf16
// ---------------------------------------------------------------------------
__global__ void transpose_w_kernel(const float* __restrict__ wA,
                                   const float* __restrict__ wD) {
    __shared__ float tile[32][33];
    const float* src = (blockIdx.z == 0) ? wA : wD;
    __nv_bfloat16* dst = g_wt[blockIdx.z];
    int lbase  = blockIdx.x * 32;
    int iobase = blockIdx.y * 32;
    int tx = threadIdx.x, ty = threadIdx.y;   // block (32, 8)
#pragma unroll
    for (int r = 0; r < 32; r += 8)
        tile[ty + r][tx] = src[(size_t)(iobase + ty + r) * LC + (lbase + tx)];
    __syncthreads();
#pragma unroll
    for (int r = 0; r < 32; r += 8)
        dst[(size_t)(lbase + ty + r) * 4096 + (iobase + tx)] =
            __float2bfloat16(tile[tx][ty + r]);
}

// ---------------------------------------------------------------------------
// Kernel 2: fused; GEMM on mma.sync bf16 3-term split.
// Grid 4096 = (k, half). 256 threads, 16 batches x 8 rows x 64 ch. 3 CTAs/SM.
// smem word map (72448 B total):
//  [0,4608)      xh2: bf16x2 k-pairs of x-hi, row-stride 36 words
//  [4608,9216)   xl2: x-lo
//  [9216,16000)  region R: ph0-2 = W_t bf16 (4096 w) + uv [2][64][21] (2688 w)
//                ph3+    = Wh2 (2304 w) + Wl2 (2304 w)  (stride-36 rows)
//  [16000,18048) corr [2][16 b][64 o]
//  [18048,18112) bias
// ---------------------------------------------------------------------------
__global__ __launch_bounds__(256, 3) void fused_kernel(
    const float* __restrict__ x, const float* __restrict__ Ws,
    const float* __restrict__ bsk, float* __restrict__ out)
{
    extern __shared__ float sm[];
    unsigned* xh2  = (unsigned*)sm;          // [128 rows][36]
    unsigned* xl2  = (unsigned*)sm + 4608;
    float*    uv   = sm + 13312;             // [2][64 i][21]
    float*    corr = sm + 16000;             // [2][16 b][64 o]
    float*    bias = sm + 18048;

    const int k    = blockIdx.x >> 1;
    const int half = blockIdx.x & 1;
    const int tid  = threadIdx.x;
    const int bl   = tid >> 4;               // 0..15 (batch within block)
    const int c4   = tid & 15;               // float4 channel group

    // ---- Phase 0a: W_t bf16 -> region R base ----
    {
        uint4* dstw = (uint4*)(sm + 9216);
#pragma unroll
        for (int it = 0; it < 2; it++) {
            int i = tid + it * 256;          // 0..511 uint4 per which
            dstw[i]       = ((const uint4*)(g_wt[0] + (size_t)k * 4096))[i];
            dstw[512 + i] = ((const uint4*)(g_wt[1] + (size_t)k * 4096))[i];
        }
    }
    if (tid < 64) bias[tid] = __ldg(bsk + tid);

    // ---- Phase 0b: x load -> bf16 hi/lo split + u/v in registers ----
    {
        const int b = half * 16 + bl;
        const float4* xg = (const float4*)(x + ((size_t)b * 16384
                                                + (size_t)k * 8) * 64) + c4;
        float4 e = make_float4(0.f, 0.f, 0.f, 0.f);
        float4 d = make_float4(0.f, 0.f, 0.f, 0.f);
#pragma unroll
        for (int j = 0; j < 8; j++) {
            float4 v = __ldg(xg + j * 16);
            unsigned h0 = pack_bf16(v.x, v.y);
            unsigned h1 = pack_bf16(v.z, v.w);
            float2 h0f = unpack_bf16(h0), h1f = unpack_bf16(h1);
            unsigned l0 = pack_bf16(v.x - h0f.x, v.y - h0f.y);
            unsigned l1 = pack_bf16(v.z - h1f.x, v.w - h1f.y);
            int base = (bl * 8 + j) * 36 + 2 * c4;
            *(uint2*)(xh2 + base) = make_uint2(h0, h1);
            *(uint2*)(xl2 + base) = make_uint2(l0, l1);
            if (j < 4) { e.x += v.x; e.y += v.y; e.z += v.z; e.w += v.w; }
            else       { d.x += v.x; d.y += v.y; d.z += v.z; d.w += v.w; }
        }
        float* up = uv + (c4 << 2) * 21 + bl;
        up[0]           = CINV * (e.x + d.x);
        up[21]          = CINV * (e.y + d.y);
        up[42]          = CINV * (e.z + d.z);
        up[63]          = CINV * (e.w + d.w);
        up[1344]        = CINV * (e.x - d.x);
        up[1344 + 21]   = CINV * (e.y - d.y);
        up[1344 + 42]   = CINV * (e.z - d.z);
        up[1344 + 63]   = CINV * (e.w - d.w);
    }
    __syncthreads();

    // ---- Phase 2: corrections (R13 proven; W_t in R, uv in R) ----
    {
        const int which = tid >> 7;
        const int r   = tid & 127;
        const int bp  = r >> 4;
        const int og  = (r & 15) * 4;
        const int b0  = 2 * bp, b1 = 2 * bp + 1;
        const __nv_bfloat16* W = (const __nv_bfloat16*)(sm + 9216) + which * 4096;
        const float* U = uv + which * 1344;

        float a0[4] = {}, a1[4] = {};
#pragma unroll 8
        for (int i = 0; i < 64; i++) {
            uint2 wv = *(const uint2*)(W + i * 64 + og);
            float2 w01 = unpack_bf16(wv.x);
            float2 w23 = unpack_bf16(wv.y);
            float u0 = U[i * 21 + b0];
            float u1 = U[i * 21 + b1];
            a0[0] = fmaf(u0, w01.x, a0[0]);
            a0[1] = fmaf(u0, w01.y, a0[1]);
            a0[2] = fmaf(u0, w23.x, a0[2]);
            a0[3] = fmaf(u0, w23.y, a0[3]);
            a1[0] = fmaf(u1, w01.x, a1[0]);
            a1[1] = fmaf(u1, w01.y, a1[1]);
            a1[2] = fmaf(u1, w23.x, a1[2]);
            a1[3] = fmaf(u1, w23.y, a1[3]);
        }
        float* cp0 = corr + which * 1024 + b0 * 64 + og;
        float* cp1 = corr + which * 1024 + b1 * 64 + og;
#pragma unroll
        for (int e = 0; e < 4; e++) {
            cp0[e] = CINV * (a0[e] - U[(og + e) * 21 + b0]);
            cp1[e] = CINV * (a1[e] - U[(og + e) * 21 + b1]);
        }
    }
    __syncthreads();   // W_t + uv dead

    // ---- Phase 3: Wh2/Wl2 = bf16 split of (W_skip + I), k-paired, stride 36
    {
        unsigned* Wh2 = (unsigned*)sm + 9216;
        unsigned* Wl2 = (unsigned*)sm + 11520;
#pragma unroll
        for (int it = 0; it < 8; it++) {
            int idx = tid + it * 256;        // 0..2047 -> (kp, c)
            int c = idx & 63, kp = idx >> 6;
            float w0 = __ldg(Ws + (2 * kp) * 64 + c) + ((2 * kp) == c ? 1.f : 0.f);
            float w1 = __ldg(Ws + (2 * kp + 1) * 64 + c) + ((2 * kp + 1) == c ? 1.f : 0.f);
            unsigned h = pack_bf16(w0, w1);
            float2 hf = unpack_bf16(h);
            unsigned l = pack_bf16(w0 - hf.x, w1 - hf.y);
            Wh2[c * 36 + kp] = h;
            Wl2[c * 36 + kp] = l;
        }
    }
    __syncthreads();

    // ---- Phase 4: mma GEMM (3-term) + epilogue ----
    {
        const unsigned* Wh2 = (unsigned*)sm + 9216;
        const unsigned* Wl2 = (unsigned*)sm + 11520;
        const int w    = tid >> 5;           // warp: batches 2w, 2w+1
        const int lane = tid & 31;
        const int g    = lane >> 2;
        const int tig  = lane & 3;
        const int rowA = ((2 * w) * 8 + g) * 36;
        const int rowB = ((2 * w + 1) * 8 + g) * 36;

        float dacc[8][4] = {};
#pragma unroll
        for (int ks = 0; ks < 4; ks++) {
            const int kb = 8 * ks;
            unsigned ah[4] = { xh2[rowA + tig + kb], xh2[rowB + tig + kb],
                               xh2[rowA + tig + 4 + kb], xh2[rowB + tig + 4 + kb] };
            unsigned al[4] = { xl2[rowA + tig + kb], xl2[rowB + tig + kb],
                               xl2[rowA + tig + 4 + kb], xl2[rowB + tig + 4 + kb] };
#pragma unroll
            for (int nt = 0; nt < 8; nt++) {
                const int cb = (nt * 8 + g) * 36 + kb;
                unsigned bh[2] = { Wh2[cb + tig], Wh2[cb + tig + 4] };
                unsigned bl2[2] = { Wl2[cb + tig], Wl2[cb + tig + 4] };
                mma_bf16(dacc[nt], ah, bh);
                mma_bf16(dacc[nt], al, bh);
                mma_bf16(dacc[nt], ah, bl2);
            }
        }

        const float sgn = (g < 4) ? 1.f : -1.f;
        const int bA = half * 16 + 2 * w;
        float* opA = out + ((size_t)bA * 16384 + (size_t)k * 8 + g) * 64;
        float* opB = out + ((size_t)(bA + 1) * 16384 + (size_t)k * 8 + g) * 64;
        const float* cA0 = corr + (2 * w) * 64;
        const float* cD0 = corr + 1024 + (2 * w) * 64;
#pragma unroll
        for (int nt = 0; nt < 8; nt++) {
            const int c = nt * 8 + 2 * tig;
            float2 bi = *(const float2*)(bias + c);
            // row A (batch 2w)
            float2 a1 = *(const float2*)(cA0 + c);
            float2 d1 = *(const float2*)(cD0 + c);
            float2 rv;
            rv.x = gelu_tanh(dacc[nt][0] + a1.x + sgn * d1.x + bi.x);
            rv.y = gelu_tanh(dacc[nt][1] + a1.y + sgn * d1.y + bi.y);
            *(float2*)(opA + c) = rv;
            // row B (batch 2w+1)
            float2 a2 = *(const float2*)(cA0 + 64 + c);
            float2 d2 = *(const float2*)(cD0 + 64 + c);
            rv.x = gelu_tanh(dacc[nt][2] + a2.x + sgn * d2.x + bi.x);
            rv.y = gelu_tanh(dacc[nt][3] + a2.y + sgn * d2.y + bi.y);
            *(float2*)(opB + c) = rv;
        }
    }
}

extern "C" void kernel_launch(void* const* d_in, const int* in_sizes, int n_in,
                              void* d_out, int out_size) {
    const float* x  = (const float*)d_in[0];   // (32, 16384, 64)
    const float* wA = (const float*)d_in[1];   // (64, 64, 2048)
    const float* wD = (const float*)d_in[2];   // (64, 64, 2048)
    const float* Ws = (const float*)d_in[3];   // (64, 64)
    const float* bs = (const float*)d_in[4];   // (64,)
    float* out = (float*)d_out;

    cudaFuncSetAttribute(fused_kernel,
        cudaFuncAttributeMaxDynamicSharedMemorySize, 72448);

    dim3 tb(32, 8), tg(LC / 32, 4096 / 32, 2);
    transpose_w_kernel<<<tg, tb>>>(wA, wD);

    fused_kernel<<<2 * LC, 256, 72448>>>(x, Ws, bs, out);
}

// round 15
// speedup vs baseline: 1.8284x; 1.0114x over previous
#include <cuda_runtime.h>
#include <cuda_bf16.h>
#include <cstdint>
#include <math.h>

#define LC   2048
#define CINV 0.35355339059327373f   // 1/(2*sqrt(2))

// Transposed wavelet weights, bf16: [which][k][i*64+o]
__device__ __nv_bfloat16 g_wt[2][(size_t)LC * 4096];

__device__ __forceinline__ float gelu_tanh(float v) {
    float z = 0.7978845608028654f * (v + 0.044715f * v * v * v);
    float t;
    asm("tanh.approx.f32 %0, %1;" : "=f"(t) : "f"(z));
    return 0.5f * v * (1.0f + t);
}

__device__ __forceinline__ unsigned pack_bf16(float a, float b) {
    __nv_bfloat162 h = __float22bfloat162_rn(make_float2(a, b));
    return *reinterpret_cast<unsigned*>(&h);
}
__device__ __forceinline__ float2 unpack_bf16(unsigned u) {
    return __bfloat1622float2(*reinterpret_cast<__nv_bfloat162*>(&u));
}

// warp mma: D(f32 m16n8) += A(bf16 m16k16, row) * B(bf16 k16n8, col)
__device__ __forceinline__ void mma_bf16(float* d, const unsigned* a, const unsigned* b) {
    asm("mma.sync.aligned.m16n8k16.row.col.f32.bf16.bf16.f32 "
        "{%0,%1,%2,%3}, {%4,%5,%6,%7}, {%8,%9}, {%0,%1,%2,%3};"
        : "+f"(d[0]), "+f"(d[1]), "+f"(d[2]), "+f"(d[3])
        : "r"(a[0]), "r"(a[1]), "r"(a[2]), "r"(a[3]), "r"(b[0]), "r"(b[1]));
}

__device__ __forceinline__ void ldmatrix_x4(unsigned* r, uint32_t addr) {
    asm volatile("ldmatrix.sync.aligned.m8n8.x4.shared.b16 {%0,%1,%2,%3}, [%4];"
        : "=r"(r[0]), "=r"(r[1]), "=r"(r[2]), "=r"(r[3]) : "r"(addr));
}

// ---------------------------------------------------------------------------
// Kernel 1: transpose w_approx / w_detail (i,o,l) -> (l, i*64+o), f32 -> bf16
// ---------------------------------------------------------------------------
__global__ void transpose_w_kernel(const float* __restrict__ wA,
                                   const float* __restrict__ wD) {
    __shared__ float tile[32][33];
    const float* src = (blockIdx.z == 0) ? wA : wD;
    __nv_bfloat16* dst = g_wt[blockIdx.z];
    int lbase  = blockIdx.x * 32;
    int iobase = blockIdx.y * 32;
    int tx = threadIdx.x, ty = threadIdx.y;   // block (32, 8)
#pragma unroll
    for (int r = 0; r < 32; r += 8)
        tile[ty + r][tx] = src[(size_t)(iobase + ty + r) * LC + (lbase + tx)];
    __syncthreads();
#pragma unroll
    for (int r = 0; r < 32; r += 8)
        dst[(size_t)(lbase + ty + r) * 4096 + (iobase + tx)] =
            __float2bfloat16(tile[tx][ty + r]);
}

// ---------------------------------------------------------------------------
// Kernel 2: fused; GEMM on mma.sync bf16 3-term split, fragments via ldmatrix.
// Grid 4096 = (k, half). 256 threads, 16 batches x 8 rows x 64 ch. 3 CTAs/SM.
// smem word map (72448 B total):
//  [0,4608)      xh2: bf16x2 k-pairs of x-hi, row-stride 36 words
//  [4608,9216)   xl2: x-lo
//  [9216,16000)  region R: ph0-2 = W_t bf16 (4096 w) + uv [2][64][21] (2688 w)
//                ph3+    = Wh2 (2304 w) + Wl2 (2304 w)  (stride-36 rows)
//  [16000,18048) corr [2][16 b][64 o]
//  [18048,18112) bias
// ---------------------------------------------------------------------------
__global__ __launch_bounds__(256, 3) void fused_kernel(
    const float* __restrict__ x, const float* __restrict__ Ws,
    const float* __restrict__ bsk, float* __restrict__ out)
{
    extern __shared__ float sm[];
    unsigned* xh2  = (unsigned*)sm;          // [128 rows][36]
    unsigned* xl2  = (unsigned*)sm + 4608;
    float*    uv   = sm + 13312;             // [2][64 i][21]
    float*    corr = sm + 16000;             // [2][16 b][64 o]
    float*    bias = sm + 18048;

    const int k    = blockIdx.x >> 1;
    const int half = blockIdx.x & 1;
    const int tid  = threadIdx.x;
    const int bl   = tid >> 4;               // 0..15 (batch within block)
    const int c4   = tid & 15;               // float4 channel group

    // ---- Phase 0a: W_t bf16 -> region R base ----
    {
        uint4* dstw = (uint4*)(sm + 9216);
#pragma unroll
        for (int it = 0; it < 2; it++) {
            int i = tid + it * 256;          // 0..511 uint4 per which
            dstw[i]       = ((const uint4*)(g_wt[0] + (size_t)k * 4096))[i];
            dstw[512 + i] = ((const uint4*)(g_wt[1] + (size_t)k * 4096))[i];
        }
    }
    if (tid < 64) bias[tid] = __ldg(bsk + tid);

    // ---- Phase 0b: x load -> bf16 hi/lo split + u/v in registers ----
    {
        const int b = half * 16 + bl;
        const float4* xg = (const float4*)(x + ((size_t)b * 16384
                                                + (size_t)k * 8) * 64) + c4;
        float4 e = make_float4(0.f, 0.f, 0.f, 0.f);
        float4 d = make_float4(0.f, 0.f, 0.f, 0.f);
#pragma unroll
        for (int j = 0; j < 8; j++) {
            float4 v = __ldg(xg + j * 16);
            unsigned h0 = pack_bf16(v.x, v.y);
            unsigned h1 = pack_bf16(v.z, v.w);
            float2 h0f = unpack_bf16(h0), h1f = unpack_bf16(h1);
            unsigned l0 = pack_bf16(v.x - h0f.x, v.y - h0f.y);
            unsigned l1 = pack_bf16(v.z - h1f.x, v.w - h1f.y);
            int base = (bl * 8 + j) * 36 + 2 * c4;
            *(uint2*)(xh2 + base) = make_uint2(h0, h1);
            *(uint2*)(xl2 + base) = make_uint2(l0, l1);
            if (j < 4) { e.x += v.x; e.y += v.y; e.z += v.z; e.w += v.w; }
            else       { d.x += v.x; d.y += v.y; d.z += v.z; d.w += v.w; }
        }
        float* up = uv + (c4 << 2) * 21 + bl;
        up[0]           = CINV * (e.x + d.x);
        up[21]          = CINV * (e.y + d.y);
        up[42]          = CINV * (e.z + d.z);
        up[63]          = CINV * (e.w + d.w);
        up[1344]        = CINV * (e.x - d.x);
        up[1344 + 21]   = CINV * (e.y - d.y);
        up[1344 + 42]   = CINV * (e.z - d.z);
        up[1344 + 63]   = CINV * (e.w - d.w);
    }
    __syncthreads();

    // ---- Phase 2: corrections (R13 proven) ----
    {
        const int which = tid >> 7;
        const int r   = tid & 127;
        const int bp  = r >> 4;
        const int og  = (r & 15) * 4;
        const int b0  = 2 * bp, b1 = 2 * bp + 1;
        const __nv_bfloat16* W = (const __nv_bfloat16*)(sm + 9216) + which * 4096;
        const float* U = uv + which * 1344;

        float a0[4] = {}, a1[4] = {};
#pragma unroll 8
        for (int i = 0; i < 64; i++) {
            uint2 wv = *(const uint2*)(W + i * 64 + og);
            float2 w01 = unpack_bf16(wv.x);
            float2 w23 = unpack_bf16(wv.y);
            float u0 = U[i * 21 + b0];
            float u1 = U[i * 21 + b1];
            a0[0] = fmaf(u0, w01.x, a0[0]);
            a0[1] = fmaf(u0, w01.y, a0[1]);
            a0[2] = fmaf(u0, w23.x, a0[2]);
            a0[3] = fmaf(u0, w23.y, a0[3]);
            a1[0] = fmaf(u1, w01.x, a1[0]);
            a1[1] = fmaf(u1, w01.y, a1[1]);
            a1[2] = fmaf(u1, w23.x, a1[2]);
            a1[3] = fmaf(u1, w23.y, a1[3]);
        }
        float* cp0 = corr + which * 1024 + b0 * 64 + og;
        float* cp1 = corr + which * 1024 + b1 * 64 + og;
#pragma unroll
        for (int e = 0; e < 4; e++) {
            cp0[e] = CINV * (a0[e] - U[(og + e) * 21 + b0]);
            cp1[e] = CINV * (a1[e] - U[(og + e) * 21 + b1]);
        }
    }
    __syncthreads();   // W_t + uv dead

    // ---- Phase 3: Wh2/Wl2 = bf16 split of (W_skip + I), k-paired, stride 36
    {
        unsigned* Wh2 = (unsigned*)sm + 9216;
        unsigned* Wl2 = (unsigned*)sm + 11520;
#pragma unroll
        for (int it = 0; it < 8; it++) {
            int idx = tid + it * 256;        // 0..2047 -> (kp, c)
            int c = idx & 63, kp = idx >> 6;
            float w0 = __ldg(Ws + (2 * kp) * 64 + c) + ((2 * kp) == c ? 1.f : 0.f);
            float w1 = __ldg(Ws + (2 * kp + 1) * 64 + c) + ((2 * kp + 1) == c ? 1.f : 0.f);
            unsigned h = pack_bf16(w0, w1);
            float2 hf = unpack_bf16(h);
            unsigned l = pack_bf16(w0 - hf.x, w1 - hf.y);
            Wh2[c * 36 + kp] = h;
            Wl2[c * 36 + kp] = l;
        }
    }
    __syncthreads();

    // ---- Phase 4: mma GEMM (3-term), fragments via ldmatrix ----
    {
        const int w    = tid >> 5;           // warp: batches 2w, 2w+1
        const int lane = tid & 31;
        const int g    = lane >> 2;
        const int tig  = lane & 3;

        // A addresses: lanes 0-7 batchA rows k0-7, 8-15 batchB rows k0-7,
        //              16-23 batchA rows k8-15, 24-31 batchB rows k8-15
        const int arow  = (2 * w + ((lane >> 3) & 1)) * 8 + (lane & 7);
        const int aoffw = arow * 36 + ((lane >> 4) << 2);
        const uint32_t aH = (uint32_t)__cvta_generic_to_shared(xh2 + aoffw);
        const uint32_t aL = aH + 4608 * 4;

        // B addresses (per nt-pair p): lanes 0-7 nt0 cols k0-7, 8-15 nt0 k8-15,
        //                              16-23 nt1 cols k0-7, 24-31 nt1 k8-15
        const int bcol  = ((lane >> 4) << 3) + (lane & 7);
        const int boffw = bcol * 36 + (((lane >> 3) & 1) << 2);
        const uint32_t bH = (uint32_t)__cvta_generic_to_shared((unsigned*)sm + 9216 + boffw);
        const uint32_t bL = bH + 2304 * 4;

        float dacc[8][4] = {};
#pragma unroll
        for (int ks = 0; ks < 4; ks++) {
            unsigned ah[4], al[4];
            ldmatrix_x4(ah, aH + ks * 32);
            ldmatrix_x4(al, aL + ks * 32);
#pragma unroll
            for (int p = 0; p < 4; p++) {
                unsigned bh[4], blo[4];
                ldmatrix_x4(bh,  bH + p * 2304 + ks * 32);
                ldmatrix_x4(blo, bL + p * 2304 + ks * 32);
                mma_bf16(dacc[2 * p],     ah, bh);
                mma_bf16(dacc[2 * p],     al, bh);
                mma_bf16(dacc[2 * p],     ah, blo);
                mma_bf16(dacc[2 * p + 1], ah, bh + 2);
                mma_bf16(dacc[2 * p + 1], al, bh + 2);
                mma_bf16(dacc[2 * p + 1], ah, blo + 2);
            }
        }

        const float sgn = (g < 4) ? 1.f : -1.f;
        const int bA = half * 16 + 2 * w;
        float* opA = out + ((size_t)bA * 16384 + (size_t)k * 8 + g) * 64;
        float* opB = out + ((size_t)(bA + 1) * 16384 + (size_t)k * 8 + g) * 64;
        const float* cA0 = corr + (2 * w) * 64;
        const float* cD0 = corr + 1024 + (2 * w) * 64;
#pragma unroll
        for (int nt = 0; nt < 8; nt++) {
            const int c = nt * 8 + 2 * tig;
            float2 bi = *(const float2*)(bias + c);
            float2 a1 = *(const float2*)(cA0 + c);
            float2 d1 = *(const float2*)(cD0 + c);
            float2 rv;
            rv.x = gelu_tanh(dacc[nt][0] + a1.x + sgn * d1.x + bi.x);
            rv.y = gelu_tanh(dacc[nt][1] + a1.y + sgn * d1.y + bi.y);
            *(float2*)(opA + c) = rv;
            float2 a2 = *(const float2*)(cA0 + 64 + c);
            float2 d2 = *(const float2*)(cD0 + 64 + c);
            rv.x = gelu_tanh(dacc[nt][2] + a2.x + sgn * d2.x + bi.x);
            rv.y = gelu_tanh(dacc[nt][3] + a2.y + sgn * d2.y + bi.y);
            *(float2*)(opB + c) = rv;
        }
    }
}

extern "C" void kernel_launch(void* const* d_in, const int* in_sizes, int n_in,
                              void* d_out, int out_size) {
    const float* x  = (const float*)d_in[0];   // (32, 16384, 64)
    const float* wA = (const float*)d_in[1];   // (64, 64, 2048)
    const float* wD = (const float*)d_in[2];   // (64, 64, 2048)
    const float* Ws = (const float*)d_in[3];   // (64, 64)
    const float* bs = (const float*)d_in[4];   // (64,)
    float* out = (float*)d_out;

    cudaFuncSetAttribute(fused_kernel,
        cudaFuncAttributeMaxDynamicSharedMemorySize, 72448);

    dim3 tb(32, 8), tg(LC / 32, 4096 / 32, 2);
    transpose_w_kernel<<<tg, tb>>>(wA, wD);

    fused_kernel<<<2 * LC, 256, 72448>>>(x, Ws, bs, out);
}

// round 16
// speedup vs baseline: 2.2153x; 1.2116x over previous
#include <cuda_runtime.h>
#include <cuda_bf16.h>
#include <cstdint>
#include <math.h>

#define LC   2048
#define CINV 0.35355339059327373f   // 1/(2*sqrt(2))

// Transposed wavelet weights, bf16: [which][k][o*64+i]  (note: o-major!)
__device__ __nv_bfloat16 g_wt[2][(size_t)LC * 4096];

// smem word offsets
#define XH2_W   0        // [128 rows][36]  x-hi bf16 k-pairs
#define XL2_W   4608     // x-lo
#define UVH_W   9216     // [32 rows][36]   uv-hi (rows 0-15 u, 16-31 v)
#define UVL_W   10368
#define WT_W    11520    // ph<=2: W_t [2][64 o][36]; ph>=3: Wh2 (2304) + Wl2 (2304)
#define CORR_W  16128    // [2][16 b][66]
#define BIAS_W  18240    // 64
#define SMEM_BYTES (18304 * 4)

__device__ __forceinline__ float gelu_tanh(float v) {
    float z = 0.7978845608028654f * (v + 0.044715f * v * v * v);
    float t;
    asm("tanh.approx.f32 %0, %1;" : "=f"(t) : "f"(z));
    return 0.5f * v * (1.0f + t);
}

__device__ __forceinline__ unsigned pack_bf16(float a, float b) {
    __nv_bfloat162 h = __float22bfloat162_rn(make_float2(a, b));
    return *reinterpret_cast<unsigned*>(&h);
}
__device__ __forceinline__ float2 unpack_bf16(unsigned u) {
    return __bfloat1622float2(*reinterpret_cast<__nv_bfloat162*>(&u));
}

__device__ __forceinline__ void mma_bf16(float* d, const unsigned* a, const unsigned* b) {
    asm("mma.sync.aligned.m16n8k16.row.col.f32.bf16.bf16.f32 "
        "{%0,%1,%2,%3}, {%4,%5,%6,%7}, {%8,%9}, {%0,%1,%2,%3};"
        : "+f"(d[0]), "+f"(d[1]), "+f"(d[2]), "+f"(d[3])
        : "r"(a[0]), "r"(a[1]), "r"(a[2]), "r"(a[3]), "r"(b[0]), "r"(b[1]));
}

__device__ __forceinline__ void ldmatrix_x4(unsigned* r, uint32_t addr) {
    asm volatile("ldmatrix.sync.aligned.m8n8.x4.shared.b16 {%0,%1,%2,%3}, [%4];"
        : "=r"(r[0]), "=r"(r[1]), "=r"(r[2]), "=r"(r[3]) : "r"(addr));
}

// ---------------------------------------------------------------------------
// Kernel 1: w[i][o][l] -> g_wt[which][l][o*64+i] bf16.
// 64 per-o-slice transposes of [i][l] -> [l][i]. grid (64 lt, 2 it, 128=which*64+o)
// ---------------------------------------------------------------------------
__global__ void transpose_w_kernel(const float* __restrict__ wA,
                                   const float* __restrict__ wD) {
    __shared__ float tile[32][33];
    const int o     = blockIdx.z & 63;
    const int which = blockIdx.z >> 6;
    const float* src = which ? wD : wA;
    __nv_bfloat16* dst = g_wt[which];
    int lbase = blockIdx.x * 32;
    int ibase = blockIdx.y * 32;
    int tx = threadIdx.x, ty = threadIdx.y;   // block (32, 8)
#pragma unroll
    for (int r = 0; r < 32; r += 8)
        tile[ty + r][tx] = src[(size_t)(ibase + ty + r) * 131072 + o * 2048 + lbase + tx];
    __syncthreads();
#pragma unroll
    for (int r = 0; r < 32; r += 8)
        dst[(size_t)(lbase + ty + r) * 4096 + o * 64 + ibase + tx] =
            __float2bfloat16(tile[tx][ty + r]);
}

// ---------------------------------------------------------------------------
// Kernel 2: fused; GEMM *and* corrections on mma.sync.
// Grid 4096 = (k, half). 256 threads, 16 batches x 8 rows x 64 ch. 3 CTAs/SM.
// ---------------------------------------------------------------------------
__global__ __launch_bounds__(256, 3) void fused_kernel(
    const float* __restrict__ x, const float* __restrict__ Ws,
    const float* __restrict__ bsk, float* __restrict__ out)
{
    extern __shared__ float sm[];
    unsigned* smw  = (unsigned*)sm;
    float*    corr = sm + CORR_W;
    float*    bias = sm + BIAS_W;

    const int k    = blockIdx.x >> 1;
    const int half = blockIdx.x & 1;
    const int tid  = threadIdx.x;
    const int bl   = tid >> 4;               // batch within block (0..15)
    const int c4   = tid & 15;               // float4 channel group

    // ---- Phase 0a: W_t bf16 -> WT region as [which][o][36 w] ----
#pragma unroll
    for (int it = 0; it < 4; it++) {
        int idx = tid + it * 256;            // 0..1023 uint4
        int which = idx >> 9, r = idx & 511;
        int o = r >> 3, wq = r & 7;
        *(uint4*)(smw + WT_W + which * 2304 + o * 36 + wq * 4) =
            ((const uint4*)(g_wt[which] + (size_t)k * 4096))[r];
    }
    if (tid < 64) bias[tid] = __ldg(bsk + tid);

    // ---- Phase 0b: x load -> bf16 hi/lo split + u/v -> bf16 hi/lo rows ----
    {
        const int b = half * 16 + bl;
        const float4* xg = (const float4*)(x + ((size_t)b * 16384
                                                + (size_t)k * 8) * 64) + c4;
        float4 e = make_float4(0.f, 0.f, 0.f, 0.f);
        float4 d = make_float4(0.f, 0.f, 0.f, 0.f);
#pragma unroll
        for (int j = 0; j < 8; j++) {
            float4 v = __ldg(xg + j * 16);
            unsigned h0 = pack_bf16(v.x, v.y);
            unsigned h1 = pack_bf16(v.z, v.w);
            float2 h0f = unpack_bf16(h0), h1f = unpack_bf16(h1);
            unsigned l0 = pack_bf16(v.x - h0f.x, v.y - h0f.y);
            unsigned l1 = pack_bf16(v.z - h1f.x, v.w - h1f.y);
            int base = (bl * 8 + j) * 36 + 2 * c4;
            *(uint2*)(smw + XH2_W + base) = make_uint2(h0, h1);
            *(uint2*)(smw + XL2_W + base) = make_uint2(l0, l1);
            if (j < 4) { e.x += v.x; e.y += v.y; e.z += v.z; e.w += v.w; }
            else       { d.x += v.x; d.y += v.y; d.z += v.z; d.w += v.w; }
        }
        float u0 = CINV * (e.x + d.x), u1 = CINV * (e.y + d.y);
        float u2 = CINV * (e.z + d.z), u3 = CINV * (e.w + d.w);
        float v0 = CINV * (e.x - d.x), v1 = CINV * (e.y - d.y);
        float v2 = CINV * (e.z - d.z), v3 = CINV * (e.w - d.w);
        unsigned uh0 = pack_bf16(u0, u1), uh1 = pack_bf16(u2, u3);
        unsigned vh0 = pack_bf16(v0, v1), vh1 = pack_bf16(v2, v3);
        float2 t0 = unpack_bf16(uh0), t1 = unpack_bf16(uh1);
        float2 s0 = unpack_bf16(vh0), s1 = unpack_bf16(vh1);
        unsigned ul0 = pack_bf16(u0 - t0.x, u1 - t0.y);
        unsigned ul1 = pack_bf16(u2 - t1.x, u3 - t1.y);
        unsigned vl0 = pack_bf16(v0 - s0.x, v1 - s0.y);
        unsigned vl1 = pack_bf16(v2 - s1.x, v3 - s1.y);
        int ru = bl * 36 + 2 * c4, rv = (16 + bl) * 36 + 2 * c4;
        *(uint2*)(smw + UVH_W + ru) = make_uint2(uh0, uh1);
        *(uint2*)(smw + UVL_W + ru) = make_uint2(ul0, ul1);
        *(uint2*)(smw + UVH_W + rv) = make_uint2(vh0, vh1);
        *(uint2*)(smw + UVL_W + rv) = make_uint2(vl0, vl1);
    }
    __syncthreads();

    // ---- Phase 2: corrections via mma. warp -> (rt = u/v, col quarter q) ----
    {
        const int w    = tid >> 5;
        const int lane = tid & 31;
        const int g    = lane >> 2;
        const int tig  = lane & 3;
        const int rt   = w & 1;              // 0: u rows / w_approx, 1: v / w_detail
        const int q    = w >> 1;             // cols 16q .. 16q+15

        const int aoffw = (rt * 16 + (lane & 15)) * 36 + ((lane >> 4) << 2);
        const uint32_t aH = (uint32_t)__cvta_generic_to_shared(smw + UVH_W + aoffw);
        const uint32_t aL = aH + 1152 * 4;

        const int bcol  = 16 * q + ((lane >> 4) << 3) + (lane & 7);
        const int boffw = bcol * 36 + (((lane >> 3) & 1) << 2);
        const uint32_t bW = (uint32_t)__cvta_generic_to_shared(
                                smw + WT_W + rt * 2304 + boffw);

        float dc[2][4] = {};
#pragma unroll
        for (int ks = 0; ks < 4; ks++) {
            unsigned ah[4], al[4], bw[4];
            ldmatrix_x4(ah, aH + ks * 32);
            ldmatrix_x4(al, aL + ks * 32);
            ldmatrix_x4(bw, bW + ks * 32);
            mma_bf16(dc[0], ah, bw);
            mma_bf16(dc[0], al, bw);
            mma_bf16(dc[1], ah, bw + 2);
            mma_bf16(dc[1], al, bw + 2);
        }

        // corr = CINV * (dc - uv);  uv recovered as uvh+uvl (exact split)
#pragma unroll
        for (int ntl = 0; ntl < 2; ntl++) {
            const int col  = 16 * q + ntl * 8 + 2 * tig;
            const int word = col >> 1;
            // batch g (tile rows 0-7)
            {
                const int row = rt * 16 + g;
                float2 uh = unpack_bf16(smw[UVH_W + row * 36 + word]);
                float2 ul = unpack_bf16(smw[UVL_W + row * 36 + word]);
                float2 cv;
                cv.x = CINV * (dc[ntl][0] - (uh.x + ul.x));
                cv.y = CINV * (dc[ntl][1] - (uh.y + ul.y));
                *(float2*)(corr + rt * 1056 + g * 66 + col) = cv;
            }
            // batch g+8 (tile rows 8-15)
            {
                const int row = rt * 16 + g + 8;
                float2 uh = unpack_bf16(smw[UVH_W + row * 36 + word]);
                float2 ul = unpack_bf16(smw[UVL_W + row * 36 + word]);
                float2 cv;
                cv.x = CINV * (dc[ntl][2] - (uh.x + ul.x));
                cv.y = CINV * (dc[ntl][3] - (uh.y + ul.y));
                *(float2*)(corr + rt * 1056 + (g + 8) * 66 + col) = cv;
            }
        }
    }
    __syncthreads();   // W_t + uv dead

    // ---- Phase 3: Wh2/Wl2 = bf16 split of (W_skip + I), k-paired, stride 36
    {
        unsigned* Wh2 = smw + WT_W;
        unsigned* Wl2 = smw + WT_W + 2304;
#pragma unroll
        for (int it = 0; it < 8; it++) {
            int idx = tid + it * 256;        // 0..2047 -> (kp, c)
            int c = idx & 63, kp = idx >> 6;
            float w0 = __ldg(Ws + (2 * kp) * 64 + c) + ((2 * kp) == c ? 1.f : 0.f);
            float w1 = __ldg(Ws + (2 * kp + 1) * 64 + c) + ((2 * kp + 1) == c ? 1.f : 0.f);
            unsigned h = pack_bf16(w0, w1);
            float2 hf = unpack_bf16(h);
            unsigned l = pack_bf16(w0 - hf.x, w1 - hf.y);
            Wh2[c * 36 + kp] = h;
            Wl2[c * 36 + kp] = l;
        }
    }
    __syncthreads();

    // ---- Phase 4: main GEMM (3-term) via ldmatrix + mma (R15 proven) ----
    {
        const int w    = tid >> 5;           // warp: batches 2w, 2w+1
        const int lane = tid & 31;
        const int g    = lane >> 2;
        const int tig  = lane & 3;

        const int arow  = (2 * w + ((lane >> 3) & 1)) * 8 + (lane & 7);
        const int aoffw = arow * 36 + ((lane >> 4) << 2);
        const uint32_t aH = (uint32_t)__cvta_generic_to_shared(smw + XH2_W + aoffw);
        const uint32_t aL = aH + 4608 * 4;

        const int bcol  = ((lane >> 4) << 3) + (lane & 7);
        const int boffw = bcol * 36 + (((lane >> 3) & 1) << 2);
        const uint32_t bH = (uint32_t)__cvta_generic_to_shared(smw + WT_W + boffw);
        const uint32_t bL = bH + 2304 * 4;

        float dacc[8][4] = {};
#pragma unroll
        for (int ks = 0; ks < 4; ks++) {
            unsigned ah[4], al[4];
            ldmatrix_x4(ah, aH + ks * 32);
            ldmatrix_x4(al, aL + ks * 32);
#pragma unroll
            for (int p = 0; p < 4; p++) {
                unsigned bh[4], blo[4];
                ldmatrix_x4(bh,  bH + p * 2304 + ks * 32);
                ldmatrix_x4(blo, bL + p * 2304 + ks * 32);
                mma_bf16(dacc[2 * p],     ah, bh);
                mma_bf16(dacc[2 * p],     al, bh);
                mma_bf16(dacc[2 * p],     ah, blo);
                mma_bf16(dacc[2 * p + 1], ah, bh + 2);
                mma_bf16(dacc[2 * p + 1], al, bh + 2);
                mma_bf16(dacc[2 * p + 1], ah, blo + 2);
            }
        }

        const float sgn = (g < 4) ? 1.f : -1.f;
        const int bA = half * 16 + 2 * w;
        float* opA = out + ((size_t)bA * 16384 + (size_t)k * 8 + g) * 64;
        float* opB = out + ((size_t)(bA + 1) * 16384 + (size_t)k * 8 + g) * 64;
        const float* cA0 = corr + (2 * w) * 66;
        const float* cD0 = corr + 1056 + (2 * w) * 66;
#pragma unroll
        for (int nt = 0; nt < 8; nt++) {
            const int c = nt * 8 + 2 * tig;
            float2 bi = *(const float2*)(bias + c);
            float2 a1 = *(const float2*)(cA0 + c);
            float2 d1 = *(const float2*)(cD0 + c);
            float2 rv;
            rv.x = gelu_tanh(dacc[nt][0] + a1.x + sgn * d1.x + bi.x);
            rv.y = gelu_tanh(dacc[nt][1] + a1.y + sgn * d1.y + bi.y);
            *(float2*)(opA + c) = rv;
            float2 a2 = *(const float2*)(cA0 + 66 + c);
            float2 d2 = *(const float2*)(cD0 + 66 + c);
            rv.x = gelu_tanh(dacc[nt][2] + a2.x + sgn * d2.x + bi.x);
            rv.y = gelu_tanh(dacc[nt][3] + a2.y + sgn * d2.y + bi.y);
            *(float2*)(opB + c) = rv;
        }
    }
}

extern "C" void kernel_launch(void* const* d_in, const int* in_sizes, int n_in,
                              void* d_out, int out_size) {
    const float* x  = (const float*)d_in[0];   // (32, 16384, 64)
    const float* wA = (const float*)d_in[1];   // (64, 64, 2048)
    const float* wD = (const float*)d_in[2];   // (64, 64, 2048)
    const float* Ws = (const float*)d_in[3];   // (64, 64)
    const float* bs = (const float*)d_in[4];   // (64,)
    float* out = (float*)d_out;

    cudaFuncSetAttribute(fused_kernel,
        cudaFuncAttributeMaxDynamicSharedMemorySize, SMEM_BYTES);

    dim3 tb(32, 8), tg(64, 2, 128);
    transpose_w_kernel<<<tg, tb>>>(wA, wD);

    fused_kernel<<<2 * LC, 256, SMEM_BYTES>>>(x, Ws, bs, out);
}